// round 14
// baseline (speedup 1.0000x reference)
#include <cuda_runtime.h>
#include <cuda_bf16.h>
#include <cuda_fp16.h>
#include <math.h>
#include <stdint.h>

#define BB 4
#define SS 2048
#define DD 1024
#define DFFN 4096
#define MM (BB*SS)
#define QKVW 3072
#define L2E 1.44269504088896f

__device__ float g_tmp[(size_t)MM * DD];
__device__ float g_res[(size_t)MM * DD];
__device__ __half g_x16[(size_t)MM * DD];
__device__ __half g_ln16[(size_t)MM * DD];
__device__ __half g_c16[(size_t)MM * DD];
__device__ __half g_f16[(size_t)MM * DFFN];
__device__ __half g_q16[(size_t)MM * DD];
__device__ __half g_k16[(size_t)MM * DD];
__device__ __half g_v16[(size_t)MM * DD];
#define W_QKV 0u
#define W_O   (3u*1024*1024)
#define W_I   (4u*1024*1024)
#define W_O2  (8u*1024*1024)
__device__ __half g_wh[12u*1024*1024];
__device__ float g_b3[QKVW];

__device__ __forceinline__ float gelu_f(float x) {
    return 0.5f * x * (1.0f + erff(x * 0.70710678118654752f));
}
__device__ __forceinline__ uint32_t s2u(const void* p) {
    uint32_t a;
    asm("{ .reg .u64 t; cvta.to.shared.u64 t, %1; cvt.u32.u64 %0, t; }" : "=r"(a) : "l"(p));
    return a;
}
__device__ __forceinline__ uint32_t swz(uint32_t off) {
    return off ^ (((off >> 7) & 7u) << 4);
}
__device__ __forceinline__ void cpa(uint32_t dst, const void* src) {
    asm volatile("cp.async.cg.shared.global [%0], [%1], 16;" :: "r"(dst), "l"(src));
}
__device__ __forceinline__ void ldsm4(uint32_t* r, uint32_t addr) {
    asm volatile("ldmatrix.sync.aligned.m8n8.x4.shared.b16 {%0,%1,%2,%3}, [%4];"
        : "=r"(r[0]), "=r"(r[1]), "=r"(r[2]), "=r"(r[3]) : "r"(addr));
}
__device__ __forceinline__ void ldsm4t(uint32_t* r, uint32_t addr) {
    asm volatile("ldmatrix.sync.aligned.m8n8.x4.trans.shared.b16 {%0,%1,%2,%3}, [%4];"
        : "=r"(r[0]), "=r"(r[1]), "=r"(r[2]), "=r"(r[3]) : "r"(addr));
}
__device__ __forceinline__ void mmaf16(float* d, const uint32_t* a, const uint32_t* b) {
    asm volatile("mma.sync.aligned.m16n8k16.row.col.f32.f16.f16.f32 "
        "{%0,%1,%2,%3}, {%4,%5,%6,%7}, {%8,%9}, {%0,%1,%2,%3};"
        : "+f"(d[0]), "+f"(d[1]), "+f"(d[2]), "+f"(d[3])
        : "r"(a[0]), "r"(a[1]), "r"(a[2]), "r"(a[3]), "r"(b[0]), "r"(b[1]));
}
// MUFU f16x2 exp2: pack (even->lo, odd->hi) then 2^x on both halves
__device__ __forceinline__ uint32_t exp2_pack(float odd, float even) {
    uint32_t p, r;
    asm("cvt.rn.f16x2.f32 %0, %1, %2;" : "=r"(p) : "f"(odd), "f"(even));
    asm("ex2.approx.f16x2 %0, %1;" : "=r"(r) : "r"(p));
    return r;
}

// ---- megaprep: 6 weight transposes + x->fp16 + bias pack, ONE launch ----
__device__ __forceinline__ void wconv_tile(const float* __restrict__ W, int N, int K,
                                           __half* __restrict__ hi, int bx, int by,
                                           int tx, int ty) {
    __shared__ float t[32][33];
    const int n0 = bx * 32, k0 = by * 32;
    for (int j = ty; j < 32; j += 8) t[j][tx] = W[(size_t)(k0 + j) * N + n0 + tx];
    __syncthreads();
    for (int j = ty; j < 32; j += 8)
        hi[(size_t)(n0 + j) * K + k0 + tx] = __float2half_rn(t[tx][j]);
}

__global__ __launch_bounds__(256)
void megaprep_kernel(const float* __restrict__ Wq, const float* __restrict__ Wk,
                     const float* __restrict__ Wv, const float* __restrict__ Wo,
                     const float* __restrict__ Wi, const float* __restrict__ Wo2,
                     const float* __restrict__ x,
                     const float* __restrict__ bq, const float* __restrict__ bk,
                     const float* __restrict__ bv,
                     __half* __restrict__ wh, __half* __restrict__ x16,
                     float* __restrict__ b3) {
    const int b = blockIdx.x;
    const int tx = threadIdx.x & 31, ty = threadIdx.x >> 5;
    if (b < 4096) {
        const int which = b >> 10, idx = b & 1023;
        const int bx = idx & 31, by = idx >> 5;
        const float* W = (which == 0) ? Wq : (which == 1) ? Wk : (which == 2) ? Wv : Wo;
        __half* dst = wh + ((which < 3) ? (W_QKV + (uint32_t)which * 1048576u) : W_O);
        wconv_tile(W, DD, DD, dst, bx, by, tx, ty);
    } else if (b < 8192) {
        const int idx = b - 4096;
        wconv_tile(Wi, DFFN, DD, wh + W_I, idx & 127, idx >> 7, tx, ty);
    } else if (b < 12288) {
        const int idx = b - 8192;
        wconv_tile(Wo2, DD, DFFN, wh + W_O2, idx & 31, idx >> 5, tx, ty);
    } else if (b < 14336) {
        const int tid = threadIdx.x;
        for (int i = (b - 12288) * 256 + tid; i < MM * DD / 4; i += 2048 * 256) {
            const float4 v = ((const float4*)x)[i];
            ((__half2*)x16)[2*i+0] = __halves2half2(__float2half_rn(v.x), __float2half_rn(v.y));
            ((__half2*)x16)[2*i+1] = __halves2half2(__float2half_rn(v.z), __float2half_rn(v.w));
        }
    } else {
        const int which = b - 14336;
        const float* s = (which == 0) ? bq : (which == 1) ? bk : bv;
        for (int i = threadIdx.x; i < 1024; i += 256)
            b3[which * 1024 + i] = s[i];
    }
}

// ---- fp16 GEMM: C[M,N] = A16[M,K] @ B16[N,K]^T + bias ----
// CTA 128x128, 512 threads (4x4 warp grid, 32x32 warp tile), BK=64,
// 3-stage cp.async, occ 2 (32 warps/SM), one sync/iter, XOR addr hoist.
#define STG_B 32768
#define T_A  0
#define T_B  16384
#define GSMEM (3*STG_B)

__device__ __forceinline__ void load_stage(uint32_t sbase,
    const __half* __restrict__ A, const __half* __restrict__ B,
    int K, int m0, int n0, int kb) {
    for (int i = threadIdx.x; i < 1024; i += 512) {
        const int row = i >> 3, cc = (i & 7) << 3;
        const uint32_t so = swz((uint32_t)(row * 128 + cc * 2));
        cpa(sbase + T_A + so, A + (size_t)(m0 + row) * K + kb + cc);
        cpa(sbase + T_B + so, B + (size_t)(n0 + row) * K + kb + cc);
    }
}

// mode 0: Cf fp32. mode 1: C16 fp16 (+act). mode 2: q/k/v fp16 out.
__global__ __launch_bounds__(512, 2)
void gemm_tc(const __half* __restrict__ A, const __half* __restrict__ B,
             const float* __restrict__ bias, float* __restrict__ Cf,
             __half* __restrict__ C16,
             __half* __restrict__ Q16, __half* __restrict__ K16, __half* __restrict__ V16,
             int N, int K, int act, int mode) {
    extern __shared__ char smv[];
    const uint32_t sb = s2u(smv);
    const int tid = threadIdx.x, lane = tid & 31, wid = tid >> 5;
    const int wm = wid & 3, wn = wid >> 2;          // 4x4 warp grid
    const int m0 = blockIdx.y << 7, n0 = blockIdx.x << 7;
    const int nc = K >> 6;

    float acc[2][4][4];
#pragma unroll
    for (int i = 0; i < 2; i++)
#pragma unroll
        for (int j = 0; j < 4; j++)
#pragma unroll
            for (int q = 0; q < 4; q++) acc[i][j][q] = 0.0f;

    load_stage(sb, A, B, K, m0, n0, 0);
    asm volatile("cp.async.commit_group;" ::: "memory");
    load_stage(sb + STG_B, A, B, K, m0, n0, 64);
    asm volatile("cp.async.commit_group;" ::: "memory");

    const int a_r = (lane & 15);
    const int a_c = (lane >> 4) << 3;
    const int b_r = (lane & 7) + ((lane >> 4) << 3);
    const int b_c = ((lane >> 3) & 1) << 3;

    // ks=0 base addresses; addr(ks) = base ^ (ks<<5)
    uint32_t aoff[2], boff[2];
#pragma unroll
    for (int mt = 0; mt < 2; mt++)
        aoff[mt] = swz((uint32_t)((wm*32 + mt*16 + a_r)*128 + a_c*2));
#pragma unroll
    for (int p = 0; p < 2; p++)
        boff[p] = swz((uint32_t)((wn*32 + p*16 + b_r)*128 + b_c*2));

    for (int c = 0; c < nc; c++) {
        asm volatile("cp.async.wait_group 1;" ::: "memory");
        __syncthreads();
        if (c + 2 < nc)
            load_stage(sb + (uint32_t)((c + 2) % 3) * STG_B, A, B, K, m0, n0, (c + 2) << 6);
        asm volatile("cp.async.commit_group;" ::: "memory");

        const uint32_t stA = sb + (uint32_t)(c % 3) * STG_B + T_A;
        const uint32_t stB = sb + (uint32_t)(c % 3) * STG_B + T_B;
#pragma unroll
        for (int ks = 0; ks < 4; ks++) {
            const uint32_t kx = (uint32_t)ks << 5;
            uint32_t af[2][4], bf[4][2];
#pragma unroll
            for (int mt = 0; mt < 2; mt++)
                ldsm4(af[mt], stA + (aoff[mt] ^ kx));
#pragma unroll
            for (int p = 0; p < 2; p++) {
                uint32_t t4[4];
                ldsm4(t4, stB + (boff[p] ^ kx));
                bf[2*p][0]=t4[0]; bf[2*p][1]=t4[1]; bf[2*p+1][0]=t4[2]; bf[2*p+1][1]=t4[3];
            }
#pragma unroll
            for (int mt = 0; mt < 2; mt++)
#pragma unroll
                for (int nt = 0; nt < 4; nt++)
                    mmaf16(acc[mt][nt], af[mt], bf[nt]);
        }
    }

    const int rbase = m0 + wm * 32 + (lane >> 2);
    const int cbase = n0 + wn * 32 + ((lane & 3) << 1);
    const int region = n0 >> 10;
#pragma unroll
    for (int mt = 0; mt < 2; mt++) {
#pragma unroll
        for (int nt = 0; nt < 4; nt++) {
            const int col = cbase + nt * 8;
            const float2 bv = *(const float2*)&bias[col];
            float v0 = acc[mt][nt][0] + bv.x, v1 = acc[mt][nt][1] + bv.y;
            float v2 = acc[mt][nt][2] + bv.x, v3 = acc[mt][nt][3] + bv.y;
            if (act) { v0 = gelu_f(v0); v1 = gelu_f(v1); v2 = gelu_f(v2); v3 = gelu_f(v3); }
            const size_t r0 = (size_t)(rbase + mt * 16);
            const size_t r1 = r0 + 8;
            if (mode == 0) {
                *(float2*)&Cf[r0 * N + col] = make_float2(v0, v1);
                *(float2*)&Cf[r1 * N + col] = make_float2(v2, v3);
            } else if (mode == 1) {
                *(__half2*)&C16[r0 * N + col] = __halves2half2(__float2half_rn(v0), __float2half_rn(v1));
                *(__half2*)&C16[r1 * N + col] = __halves2half2(__float2half_rn(v2), __float2half_rn(v3));
            } else {
                const size_t cl_ = (size_t)(col - (region << 10));
                __half* D = (region == 0) ? Q16 : (region == 1) ? K16 : V16;
                *(__half2*)&D[r0 * DD + cl_] = __halves2half2(__float2half_rn(v0), __float2half_rn(v1));
                *(__half2*)&D[r1 * DD + cl_] = __halves2half2(__float2half_rn(v2), __float2half_rn(v3));
            }
        }
    }
}

// ---- fp16 flash attention: 128 q-rows/CTA, MUFU f16x2 exp, occ 2, 1 sync/iter ----
#define AT_Q 0
#define AT_ST 16384
#define AT_SSZ 16640
#define AT_SMEM (16384 + 3*16640)

__global__ __launch_bounds__(256, 2)
void attn_mma(const __half* __restrict__ q16, const __half* __restrict__ k16,
              const __half* __restrict__ v16, const float* __restrict__ mask,
              __half* __restrict__ c16) {
    extern __shared__ char smv[];
    const uint32_t sb = s2u(smv);
    const int tid = threadIdx.x, lane = tid & 31, wid = tid >> 5;
    const int b = blockIdx.y >> 4, h = blockIdx.y & 15;
    const int q0 = blockIdx.x << 7;
    const size_t hoff = (size_t)h * 64;

    for (int i = tid; i < 1024; i += 256) {
        const int row = i >> 3, cc = i & 7;
        cpa(sb + AT_Q + swz((uint32_t)(row*128 + cc*16)),
            q16 + (size_t)(b*SS + q0 + row)*DD + hoff + cc*8);
    }
    for (int sidx = 0; sidx < 2; sidx++) {
        const int kt = sidx << 6;
        const uint32_t base = sb + AT_ST + (uint32_t)sidx * AT_SSZ;
        for (int i = tid; i < 1024; i += 256) {
            const int t = i >> 9, idx = i & 511, row = idx >> 3, cc = idx & 7;
            const __half* src = (t ? v16 : k16) + (size_t)(b*SS + kt + row)*DD + hoff + cc*8;
            cpa(base + t*8192 + swz((uint32_t)(row*128 + cc*16)), src);
        }
        if (tid < 16) cpa(base + 16384 + tid*16, mask + (size_t)b*SS + kt + tid*4);
        asm volatile("cp.async.commit_group;" ::: "memory");
    }

    uint32_t qf[4][4];
    float o[8][4], lacc[4];
    float mL0 = -1e30f, mL1 = -1e30f;
#pragma unroll
    for (int nt = 0; nt < 8; nt++) { o[nt][0]=o[nt][1]=o[nt][2]=o[nt][3]=0.f; }
    lacc[0]=lacc[1]=lacc[2]=lacc[3]=0.f;
    const uint32_t ones2[2] = {0x3C003C00u, 0x3C003C00u};

    uint32_t kboff[4];
#pragma unroll
    for (int p = 0; p < 4; p++)
        kboff[p] = swz((uint32_t)((p*16 + (lane & 7) + ((lane >> 4) << 3))*128
                                  + ((((lane >> 3) & 1) << 3)) * 2));
    const uint32_t vboff = swz((uint32_t)((lane & 15)*128 + (((lane >> 4) << 3)) * 2));

    for (int c = 0; c < SS/64; c++) {
        asm volatile("cp.async.wait_group 1;" ::: "memory");
        __syncthreads();
        if (c + 2 < SS/64) {
            const int kt = (c + 2) << 6;
            const uint32_t base = sb + AT_ST + (uint32_t)((c+2) % 3) * AT_SSZ;
            for (int i = tid; i < 1024; i += 256) {
                const int t = i >> 9, idx = i & 511, row = idx >> 3, cc = idx & 7;
                const __half* src = (t ? v16 : k16) + (size_t)(b*SS + kt + row)*DD + hoff + cc*8;
                cpa(base + t*8192 + swz((uint32_t)(row*128 + cc*16)), src);
            }
            if (tid < 16) cpa(base + 16384 + tid*16, mask + (size_t)b*SS + kt + tid*4);
        }
        asm volatile("cp.async.commit_group;" ::: "memory");

        if (c == 0) {
#pragma unroll
            for (int ks = 0; ks < 4; ks++) {
                const int row = wid*16 + (lane & 15);
                const int colb = (ks*16 + ((lane >> 4) << 3)) * 2;
                ldsm4(qf[ks], sb + AT_Q + swz((uint32_t)(row*128 + colb)));
            }
        }

        const uint32_t soff = AT_ST + (uint32_t)(c % 3) * AT_SSZ;
        const uint32_t st = sb + soff;
        float S[8][4];
#pragma unroll
        for (int nt = 0; nt < 8; nt++) { S[nt][0]=S[nt][1]=S[nt][2]=S[nt][3]=0.f; }
#pragma unroll
        for (int ks = 0; ks < 4; ks++) {
            const uint32_t kx = (uint32_t)ks << 5;
            uint32_t kb[8][2];
#pragma unroll
            for (int p = 0; p < 4; p++) {
                uint32_t t4[4];
                ldsm4(t4, st + (kboff[p] ^ kx));
                kb[2*p][0]=t4[0]; kb[2*p][1]=t4[1]; kb[2*p+1][0]=t4[2]; kb[2*p+1][1]=t4[3];
            }
#pragma unroll
            for (int nt = 0; nt < 8; nt++)
                mmaf16(S[nt], qf[ks], kb[nt]);
        }
#pragma unroll
        for (int nt = 0; nt < 8; nt++) {
            const float2 mv = *(const float2*)(smv + soff + 16384 + (8*nt + 2*(lane&3))*4);
            S[nt][0] = fmaf(S[nt][0], 0.125f, mv.x);
            S[nt][1] = fmaf(S[nt][1], 0.125f, mv.y);
            S[nt][2] = fmaf(S[nt][2], 0.125f, mv.x);
            S[nt][3] = fmaf(S[nt][3], 0.125f, mv.y);
        }
        float mx0 = -1e30f, mx1 = -1e30f;
#pragma unroll
        for (int nt = 0; nt < 8; nt++) {
            mx0 = fmaxf(mx0, fmaxf(S[nt][0], S[nt][1]));
            mx1 = fmaxf(mx1, fmaxf(S[nt][2], S[nt][3]));
        }
        mx0 = fmaxf(mx0, __shfl_xor_sync(~0u, mx0, 1));
        mx0 = fmaxf(mx0, __shfl_xor_sync(~0u, mx0, 2));
        mx1 = fmaxf(mx1, __shfl_xor_sync(~0u, mx1, 1));
        mx1 = fmaxf(mx1, __shfl_xor_sync(~0u, mx1, 2));
        const float mLn0 = fmaxf(mL0, mx0 * L2E);
        const float mLn1 = fmaxf(mL1, mx1 * L2E);
        const float corr0 = exp2f(mL0 - mLn0);
        const float corr1 = exp2f(mL1 - mLn1);
        mL0 = mLn0; mL1 = mLn1;
        lacc[0] *= corr0; lacc[1] *= corr0; lacc[2] *= corr1; lacc[3] *= corr1;
#pragma unroll
        for (int nt = 0; nt < 8; nt++) {
            o[nt][0] *= corr0; o[nt][1] *= corr0; o[nt][2] *= corr1; o[nt][3] *= corr1;
        }
        uint32_t pf[4][4];
#pragma unroll
        for (int j = 0; j < 4; j++) {
            pf[j][0] = exp2_pack(fmaf(S[2*j][1],   L2E, -mL0), fmaf(S[2*j][0],   L2E, -mL0));
            pf[j][1] = exp2_pack(fmaf(S[2*j][3],   L2E, -mL1), fmaf(S[2*j][2],   L2E, -mL1));
            pf[j][2] = exp2_pack(fmaf(S[2*j+1][1], L2E, -mL0), fmaf(S[2*j+1][0], L2E, -mL0));
            pf[j][3] = exp2_pack(fmaf(S[2*j+1][3], L2E, -mL1), fmaf(S[2*j+1][2], L2E, -mL1));
        }
#pragma unroll
        for (int j = 0; j < 4; j++) mmaf16(lacc, pf[j], ones2);
#pragma unroll
        for (int j = 0; j < 4; j++) {
            const uint32_t vbase = st + 8192 + (uint32_t)(j * 2048);
#pragma unroll
            for (int pp = 0; pp < 4; pp++) {
                uint32_t vf[4];
                ldsm4t(vf, vbase + (vboff ^ ((uint32_t)pp << 5)));
                mmaf16(o[2*pp],   pf[j], vf);
                mmaf16(o[2*pp+1], pf[j], vf + 2);
            }
        }
    }

    const float inv0 = 1.0f / lacc[0];
    const float inv1 = 1.0f / lacc[2];
    const size_t r0 = (size_t)(b*SS + q0 + wid*16 + (lane >> 2));
    const size_t r1 = r0 + 8;
#pragma unroll
    for (int nt = 0; nt < 8; nt++) {
        const size_t col = hoff + 8*nt + 2*(lane & 3);
        *(__half2*)&c16[r0*DD + col] = __halves2half2(
            __float2half_rn(o[nt][0]*inv0), __float2half_rn(o[nt][1]*inv0));
        *(__half2*)&c16[r1*DD + col] = __halves2half2(
            __float2half_rn(o[nt][2]*inv1), __float2half_rn(o[nt][3]*inv1));
    }
}

// ---- warp-per-row LayerNorm: shuffle-only, no smem/bar ----
__global__ __launch_bounds__(256)
void ln_kernel(const float* __restrict__ Y, const float* __restrict__ R,
               const float* __restrict__ g, const float* __restrict__ bta,
               float* __restrict__ out, __half* __restrict__ h16) {
    const int row = blockIdx.x * 8 + (threadIdx.x >> 5);
    const int lane = threadIdx.x & 31;
    const float4* yp = (const float4*)(Y + (size_t)row * DD);
    const float4* rp = (const float4*)(R + (size_t)row * DD);

    float4 v[8];
    float s = 0.0f;
#pragma unroll
    for (int j = 0; j < 8; j++) {
        float4 a = yp[lane + 32 * j];
        const float4 b = rp[lane + 32 * j];
        a.x += b.x; a.y += b.y; a.z += b.z; a.w += b.w;
        v[j] = a;
        s += a.x + a.y + a.z + a.w;
    }
#pragma unroll
    for (int off = 16; off; off >>= 1) s += __shfl_xor_sync(~0u, s, off);
    const float mean = s * (1.0f / 1024.0f);

    float s2 = 0.0f;
#pragma unroll
    for (int j = 0; j < 8; j++) {
        const float dx = v[j].x - mean, dy = v[j].y - mean;
        const float dz = v[j].z - mean, dw = v[j].w - mean;
        s2 += dx*dx + dy*dy + dz*dz + dw*dw;
    }
#pragma unroll
    for (int off = 16; off; off >>= 1) s2 += __shfl_xor_sync(~0u, s2, off);
    const float rstd = rsqrtf(s2 * (1.0f / 1024.0f) + 1e-12f);

    float4* op = (float4*)(out + (size_t)row * DD);
#pragma unroll
    for (int j = 0; j < 8; j++) {
        const int idx = lane + 32 * j;
        const float4 gg = ((const float4*)g)[idx];
        const float4 bb = ((const float4*)bta)[idx];
        float4 o;
        o.x = (v[j].x - mean) * rstd * gg.x + bb.x;
        o.y = (v[j].y - mean) * rstd * gg.y + bb.y;
        o.z = (v[j].z - mean) * rstd * gg.z + bb.z;
        o.w = (v[j].w - mean) * rstd * gg.w + bb.w;
        op[idx] = o;
        if (h16) {
            ((__half2*)(h16 + (size_t)row * DD))[2*idx] =
                __halves2half2(__float2half_rn(o.x), __float2half_rn(o.y));
            ((__half2*)(h16 + (size_t)row * DD))[2*idx+1] =
                __halves2half2(__float2half_rn(o.z), __float2half_rn(o.w));
        }
    }
}

extern "C" void kernel_launch(void* const* d_in, const int* in_sizes, int n_in,
                              void* d_out, int out_size) {
    const float* x    = (const float*)d_in[0];
    const float* mask = (const float*)d_in[1];
    const float* Wq = (const float*)d_in[2];  const float* bq = (const float*)d_in[3];
    const float* Wk = (const float*)d_in[4];  const float* bk = (const float*)d_in[5];
    const float* Wv = (const float*)d_in[6];  const float* bv = (const float*)d_in[7];
    const float* Wo = (const float*)d_in[8];  const float* bo = (const float*)d_in[9];
    const float* ln1g = (const float*)d_in[10]; const float* ln1b = (const float*)d_in[11];
    const float* Wi = (const float*)d_in[12]; const float* bi = (const float*)d_in[13];
    const float* Wo2 = (const float*)d_in[14]; const float* bo2 = (const float*)d_in[15];
    const float* ln2g = (const float*)d_in[16]; const float* ln2b = (const float*)d_in[17];
    float* out = (float*)d_out;

    float *tmp, *res, *b3;
    __half *x16, *ln16, *c16, *f16, *q16, *k16, *v16, *wh;
    cudaGetSymbolAddress((void**)&tmp, g_tmp);
    cudaGetSymbolAddress((void**)&res, g_res);
    cudaGetSymbolAddress((void**)&b3, g_b3);
    cudaGetSymbolAddress((void**)&x16, g_x16);
    cudaGetSymbolAddress((void**)&ln16, g_ln16);
    cudaGetSymbolAddress((void**)&c16, g_c16);
    cudaGetSymbolAddress((void**)&f16, g_f16);
    cudaGetSymbolAddress((void**)&q16, g_q16);
    cudaGetSymbolAddress((void**)&k16, g_k16);
    cudaGetSymbolAddress((void**)&v16, g_v16);
    cudaGetSymbolAddress((void**)&wh, g_wh);

    cudaFuncSetAttribute(gemm_tc, cudaFuncAttributeMaxDynamicSharedMemorySize, GSMEM);
    cudaFuncSetAttribute(attn_mma, cudaFuncAttributeMaxDynamicSharedMemorySize, AT_SMEM);

    megaprep_kernel<<<14339, 256>>>(Wq, Wk, Wv, Wo, Wi, Wo2, x, bq, bk, bv, wh, x16, b3);

    gemm_tc<<<dim3(QKVW/128, MM/128), 512, GSMEM>>>(x16, wh + W_QKV, b3,
        0, 0, q16, k16, v16, QKVW, DD, 0, 2);
    attn_mma<<<dim3(SS/128, BB*16), 256, AT_SMEM>>>(q16, k16, v16, mask, c16);
    gemm_tc<<<dim3(DD/128, MM/128), 512, GSMEM>>>(c16, wh + W_O, bo,
        tmp, 0, 0, 0, 0, DD, DD, 0, 0);
    ln_kernel<<<MM/8, 256>>>(tmp, x, ln1g, ln1b, res, ln16);
    gemm_tc<<<dim3(DFFN/128, MM/128), 512, GSMEM>>>(ln16, wh + W_I, bi,
        0, f16, 0, 0, 0, DFFN, DD, 1, 1);
    gemm_tc<<<dim3(DD/128, MM/128), 512, GSMEM>>>(f16, wh + W_O2, bo2,
        tmp, 0, 0, 0, 0, DD, DFFN, 0, 0);
    ln_kernel<<<MM/8, 256>>>(tmp, res, ln2g, ln2b, out, 0);
}

// round 15
// speedup vs baseline: 1.0422x; 1.0422x over previous
#include <cuda_runtime.h>
#include <cuda_bf16.h>
#include <cuda_fp16.h>
#include <math.h>
#include <stdint.h>

#define BB 4
#define SS 2048
#define DD 1024
#define DFFN 4096
#define MM (BB*SS)
#define QKVW 3072
#define L2E 1.44269504088896f

__device__ float g_tmp[(size_t)MM * DD];
__device__ float g_res[(size_t)MM * DD];
__device__ __half g_x16[(size_t)MM * DD];
__device__ __half g_ln16[(size_t)MM * DD];
__device__ __half g_c16[(size_t)MM * DD];
__device__ __half g_f16[(size_t)MM * DFFN];
__device__ __half g_q16[(size_t)MM * DD];
__device__ __half g_k16[(size_t)MM * DD];
__device__ __half g_v16[(size_t)MM * DD];
#define W_QKV 0u
#define W_O   (3u*1024*1024)
#define W_I   (4u*1024*1024)
#define W_O2  (8u*1024*1024)
__device__ __half g_wh[12u*1024*1024];
__device__ float g_b3[QKVW];

__device__ __forceinline__ float gelu_f(float x) {
    return 0.5f * x * (1.0f + erff(x * 0.70710678118654752f));
}
__device__ __forceinline__ uint32_t s2u(const void* p) {
    uint32_t a;
    asm("{ .reg .u64 t; cvta.to.shared.u64 t, %1; cvt.u32.u64 %0, t; }" : "=r"(a) : "l"(p));
    return a;
}
__device__ __forceinline__ uint32_t swz(uint32_t off) {
    return off ^ (((off >> 7) & 7u) << 4);
}
__device__ __forceinline__ void cpa(uint32_t dst, const void* src) {
    asm volatile("cp.async.cg.shared.global [%0], [%1], 16;" :: "r"(dst), "l"(src));
}
__device__ __forceinline__ void ldsm4(uint32_t* r, uint32_t addr) {
    asm volatile("ldmatrix.sync.aligned.m8n8.x4.shared.b16 {%0,%1,%2,%3}, [%4];"
        : "=r"(r[0]), "=r"(r[1]), "=r"(r[2]), "=r"(r[3]) : "r"(addr));
}
__device__ __forceinline__ void ldsm4t(uint32_t* r, uint32_t addr) {
    asm volatile("ldmatrix.sync.aligned.m8n8.x4.trans.shared.b16 {%0,%1,%2,%3}, [%4];"
        : "=r"(r[0]), "=r"(r[1]), "=r"(r[2]), "=r"(r[3]) : "r"(addr));
}
__device__ __forceinline__ void mmaf16(float* d, const uint32_t* a, const uint32_t* b) {
    asm volatile("mma.sync.aligned.m16n8k16.row.col.f32.f16.f16.f32 "
        "{%0,%1,%2,%3}, {%4,%5,%6,%7}, {%8,%9}, {%0,%1,%2,%3};"
        : "+f"(d[0]), "+f"(d[1]), "+f"(d[2]), "+f"(d[3])
        : "r"(a[0]), "r"(a[1]), "r"(a[2]), "r"(a[3]), "r"(b[0]), "r"(b[1]));
}
// MUFU f16x2 exp2: pack (even->lo, odd->hi) then 2^x on both halves
__device__ __forceinline__ uint32_t exp2_pack(float odd, float even) {
    uint32_t p, r;
    asm("cvt.rn.f16x2.f32 %0, %1, %2;" : "=r"(p) : "f"(odd), "f"(even));
    asm("ex2.approx.f16x2 %0, %1;" : "=r"(r) : "r"(p));
    return r;
}

// ---- megaprep: 6 weight transposes + x->fp16 + bias pack, ONE launch ----
__device__ __forceinline__ void wconv_tile(const float* __restrict__ W, int N, int K,
                                           __half* __restrict__ hi, int bx, int by,
                                           int tx, int ty) {
    __shared__ float t[32][33];
    const int n0 = bx * 32, k0 = by * 32;
    for (int j = ty; j < 32; j += 8) t[j][tx] = W[(size_t)(k0 + j) * N + n0 + tx];
    __syncthreads();
    for (int j = ty; j < 32; j += 8)
        hi[(size_t)(n0 + j) * K + k0 + tx] = __float2half_rn(t[tx][j]);
}

__global__ __launch_bounds__(256)
void megaprep_kernel(const float* __restrict__ Wq, const float* __restrict__ Wk,
                     const float* __restrict__ Wv, const float* __restrict__ Wo,
                     const float* __restrict__ Wi, const float* __restrict__ Wo2,
                     const float* __restrict__ x,
                     const float* __restrict__ bq, const float* __restrict__ bk,
                     const float* __restrict__ bv,
                     __half* __restrict__ wh, __half* __restrict__ x16,
                     float* __restrict__ b3) {
    const int b = blockIdx.x;
    const int tx = threadIdx.x & 31, ty = threadIdx.x >> 5;
    if (b < 4096) {
        const int which = b >> 10, idx = b & 1023;
        const int bx = idx & 31, by = idx >> 5;
        const float* W = (which == 0) ? Wq : (which == 1) ? Wk : (which == 2) ? Wv : Wo;
        __half* dst = wh + ((which < 3) ? (W_QKV + (uint32_t)which * 1048576u) : W_O);
        wconv_tile(W, DD, DD, dst, bx, by, tx, ty);
    } else if (b < 8192) {
        const int idx = b - 4096;
        wconv_tile(Wi, DFFN, DD, wh + W_I, idx & 127, idx >> 7, tx, ty);
    } else if (b < 12288) {
        const int idx = b - 8192;
        wconv_tile(Wo2, DD, DFFN, wh + W_O2, idx & 31, idx >> 5, tx, ty);
    } else if (b < 14336) {
        const int tid = threadIdx.x;
        for (int i = (b - 12288) * 256 + tid; i < MM * DD / 4; i += 2048 * 256) {
            const float4 v = ((const float4*)x)[i];
            ((__half2*)x16)[2*i+0] = __halves2half2(__float2half_rn(v.x), __float2half_rn(v.y));
            ((__half2*)x16)[2*i+1] = __halves2half2(__float2half_rn(v.z), __float2half_rn(v.w));
        }
    } else {
        const int which = b - 14336;
        const float* s = (which == 0) ? bq : (which == 1) ? bk : bv;
        for (int i = threadIdx.x; i < 1024; i += 256)
            b3[which * 1024 + i] = s[i];
    }
}

// ---- fp16 GEMM: C[M,N] = A16[M,K] @ B16[N,K]^T + bias ----
// CTA 128x128, 128 threads (2x2 warp grid, 64x64 warp tile), BK=64,
// 3-stage cp.async, occ 2 (8 warps/SM), one sync/iter, XOR addr hoist.
// ldsm/mma = 0.25 (vs 0.375 in the 8-warp variant) to relieve the LDS crossbar.
#define STG_B 32768
#define T_A  0
#define T_B  16384
#define GSMEM (3*STG_B)

__device__ __forceinline__ void load_stage(uint32_t sbase,
    const __half* __restrict__ A, const __half* __restrict__ B,
    int K, int m0, int n0, int kb) {
    for (int i = threadIdx.x; i < 1024; i += 128) {
        const int row = i >> 3, cc = (i & 7) << 3;
        const uint32_t so = swz((uint32_t)(row * 128 + cc * 2));
        cpa(sbase + T_A + so, A + (size_t)(m0 + row) * K + kb + cc);
        cpa(sbase + T_B + so, B + (size_t)(n0 + row) * K + kb + cc);
    }
}

// mode 0: Cf fp32. mode 1: C16 fp16 (+act). mode 2: q/k/v fp16 out.
__global__ __launch_bounds__(128, 2)
void gemm_tc(const __half* __restrict__ A, const __half* __restrict__ B,
             const float* __restrict__ bias, float* __restrict__ Cf,
             __half* __restrict__ C16,
             __half* __restrict__ Q16, __half* __restrict__ K16, __half* __restrict__ V16,
             int N, int K, int act, int mode) {
    extern __shared__ char smv[];
    const uint32_t sb = s2u(smv);
    const int tid = threadIdx.x, lane = tid & 31, wid = tid >> 5;
    const int wm = wid & 1, wn = wid >> 1;          // 2x2 warp grid, 64x64 tiles
    const int m0 = blockIdx.y << 7, n0 = blockIdx.x << 7;
    const int nc = K >> 6;

    float acc[4][8][4];
#pragma unroll
    for (int i = 0; i < 4; i++)
#pragma unroll
        for (int j = 0; j < 8; j++)
#pragma unroll
            for (int q = 0; q < 4; q++) acc[i][j][q] = 0.0f;

    load_stage(sb, A, B, K, m0, n0, 0);
    asm volatile("cp.async.commit_group;" ::: "memory");
    load_stage(sb + STG_B, A, B, K, m0, n0, 64);
    asm volatile("cp.async.commit_group;" ::: "memory");

    const int a_r = (lane & 15);
    const int a_c = (lane >> 4) << 3;
    const int b_r = (lane & 7) + ((lane >> 4) << 3);
    const int b_c = ((lane >> 3) & 1) << 3;

    // ks=0 base addresses; addr(ks) = base ^ (ks<<5)
    uint32_t aoff[4], boff[4];
#pragma unroll
    for (int mt = 0; mt < 4; mt++)
        aoff[mt] = swz((uint32_t)((wm*64 + mt*16 + a_r)*128 + a_c*2));
#pragma unroll
    for (int p = 0; p < 4; p++)
        boff[p] = swz((uint32_t)((wn*64 + p*16 + b_r)*128 + b_c*2));

    for (int c = 0; c < nc; c++) {
        asm volatile("cp.async.wait_group 1;" ::: "memory");
        __syncthreads();
        if (c + 2 < nc)
            load_stage(sb + (uint32_t)((c + 2) % 3) * STG_B, A, B, K, m0, n0, (c + 2) << 6);
        asm volatile("cp.async.commit_group;" ::: "memory");

        const uint32_t stA = sb + (uint32_t)(c % 3) * STG_B + T_A;
        const uint32_t stB = sb + (uint32_t)(c % 3) * STG_B + T_B;
#pragma unroll
        for (int ks = 0; ks < 4; ks++) {
            const uint32_t kx = (uint32_t)ks << 5;
            uint32_t af[4][4], bf[8][2];
#pragma unroll
            for (int mt = 0; mt < 4; mt++)
                ldsm4(af[mt], stA + (aoff[mt] ^ kx));
#pragma unroll
            for (int p = 0; p < 4; p++) {
                uint32_t t4[4];
                ldsm4(t4, stB + (boff[p] ^ kx));
                bf[2*p][0]=t4[0]; bf[2*p][1]=t4[1]; bf[2*p+1][0]=t4[2]; bf[2*p+1][1]=t4[3];
            }
#pragma unroll
            for (int mt = 0; mt < 4; mt++)
#pragma unroll
                for (int nt = 0; nt < 8; nt++)
                    mmaf16(acc[mt][nt], af[mt], bf[nt]);
        }
    }

    const int rbase = m0 + wm * 64 + (lane >> 2);
    const int cbase = n0 + wn * 64 + ((lane & 3) << 1);
    const int region = n0 >> 10;
#pragma unroll
    for (int mt = 0; mt < 4; mt++) {
#pragma unroll
        for (int nt = 0; nt < 8; nt++) {
            const int col = cbase + nt * 8;
            const float2 bv = *(const float2*)&bias[col];
            float v0 = acc[mt][nt][0] + bv.x, v1 = acc[mt][nt][1] + bv.y;
            float v2 = acc[mt][nt][2] + bv.x, v3 = acc[mt][nt][3] + bv.y;
            if (act) { v0 = gelu_f(v0); v1 = gelu_f(v1); v2 = gelu_f(v2); v3 = gelu_f(v3); }
            const size_t r0 = (size_t)(rbase + mt * 16);
            const size_t r1 = r0 + 8;
            if (mode == 0) {
                *(float2*)&Cf[r0 * N + col] = make_float2(v0, v1);
                *(float2*)&Cf[r1 * N + col] = make_float2(v2, v3);
            } else if (mode == 1) {
                *(__half2*)&C16[r0 * N + col] = __halves2half2(__float2half_rn(v0), __float2half_rn(v1));
                *(__half2*)&C16[r1 * N + col] = __halves2half2(__float2half_rn(v2), __float2half_rn(v3));
            } else {
                const size_t cl_ = (size_t)(col - (region << 10));
                __half* D = (region == 0) ? Q16 : (region == 1) ? K16 : V16;
                *(__half2*)&D[r0 * DD + cl_] = __halves2half2(__float2half_rn(v0), __float2half_rn(v1));
                *(__half2*)&D[r1 * DD + cl_] = __halves2half2(__float2half_rn(v2), __float2half_rn(v3));
            }
        }
    }
}

// ---- fp16 flash attention: 128 q-rows/CTA, MUFU f16x2 exp, occ 2, 1 sync/iter ----
#define AT_Q 0
#define AT_ST 16384
#define AT_SSZ 16640
#define AT_SMEM (16384 + 3*16640)

__global__ __launch_bounds__(256, 2)
void attn_mma(const __half* __restrict__ q16, const __half* __restrict__ k16,
              const __half* __restrict__ v16, const float* __restrict__ mask,
              __half* __restrict__ c16) {
    extern __shared__ char smv[];
    const uint32_t sb = s2u(smv);
    const int tid = threadIdx.x, lane = tid & 31, wid = tid >> 5;
    const int b = blockIdx.y >> 4, h = blockIdx.y & 15;
    const int q0 = blockIdx.x << 7;
    const size_t hoff = (size_t)h * 64;

    for (int i = tid; i < 1024; i += 256) {
        const int row = i >> 3, cc = i & 7;
        cpa(sb + AT_Q + swz((uint32_t)(row*128 + cc*16)),
            q16 + (size_t)(b*SS + q0 + row)*DD + hoff + cc*8);
    }
    for (int sidx = 0; sidx < 2; sidx++) {
        const int kt = sidx << 6;
        const uint32_t base = sb + AT_ST + (uint32_t)sidx * AT_SSZ;
        for (int i = tid; i < 1024; i += 256) {
            const int t = i >> 9, idx = i & 511, row = idx >> 3, cc = idx & 7;
            const __half* src = (t ? v16 : k16) + (size_t)(b*SS + kt + row)*DD + hoff + cc*8;
            cpa(base + t*8192 + swz((uint32_t)(row*128 + cc*16)), src);
        }
        if (tid < 16) cpa(base + 16384 + tid*16, mask + (size_t)b*SS + kt + tid*4);
        asm volatile("cp.async.commit_group;" ::: "memory");
    }

    uint32_t qf[4][4];
    float o[8][4], lacc[4];
    float mL0 = -1e30f, mL1 = -1e30f;
#pragma unroll
    for (int nt = 0; nt < 8; nt++) { o[nt][0]=o[nt][1]=o[nt][2]=o[nt][3]=0.f; }
    lacc[0]=lacc[1]=lacc[2]=lacc[3]=0.f;
    const uint32_t ones2[2] = {0x3C003C00u, 0x3C003C00u};

    uint32_t kboff[4];
#pragma unroll
    for (int p = 0; p < 4; p++)
        kboff[p] = swz((uint32_t)((p*16 + (lane & 7) + ((lane >> 4) << 3))*128
                                  + ((((lane >> 3) & 1) << 3)) * 2));
    const uint32_t vboff = swz((uint32_t)((lane & 15)*128 + (((lane >> 4) << 3)) * 2));

    for (int c = 0; c < SS/64; c++) {
        asm volatile("cp.async.wait_group 1;" ::: "memory");
        __syncthreads();
        if (c + 2 < SS/64) {
            const int kt = (c + 2) << 6;
            const uint32_t base = sb + AT_ST + (uint32_t)((c+2) % 3) * AT_SSZ;
            for (int i = tid; i < 1024; i += 256) {
                const int t = i >> 9, idx = i & 511, row = idx >> 3, cc = idx & 7;
                const __half* src = (t ? v16 : k16) + (size_t)(b*SS + kt + row)*DD + hoff + cc*8;
                cpa(base + t*8192 + swz((uint32_t)(row*128 + cc*16)), src);
            }
            if (tid < 16) cpa(base + 16384 + tid*16, mask + (size_t)b*SS + kt + tid*4);
        }
        asm volatile("cp.async.commit_group;" ::: "memory");

        if (c == 0) {
#pragma unroll
            for (int ks = 0; ks < 4; ks++) {
                const int row = wid*16 + (lane & 15);
                const int colb = (ks*16 + ((lane >> 4) << 3)) * 2;
                ldsm4(qf[ks], sb + AT_Q + swz((uint32_t)(row*128 + colb)));
            }
        }

        const uint32_t soff = AT_ST + (uint32_t)(c % 3) * AT_SSZ;
        const uint32_t st = sb + soff;
        float S[8][4];
#pragma unroll
        for (int nt = 0; nt < 8; nt++) { S[nt][0]=S[nt][1]=S[nt][2]=S[nt][3]=0.f; }
#pragma unroll
        for (int ks = 0; ks < 4; ks++) {
            const uint32_t kx = (uint32_t)ks << 5;
            uint32_t kb[8][2];
#pragma unroll
            for (int p = 0; p < 4; p++) {
                uint32_t t4[4];
                ldsm4(t4, st + (kboff[p] ^ kx));
                kb[2*p][0]=t4[0]; kb[2*p][1]=t4[1]; kb[2*p+1][0]=t4[2]; kb[2*p+1][1]=t4[3];
            }
#pragma unroll
            for (int nt = 0; nt < 8; nt++)
                mmaf16(S[nt], qf[ks], kb[nt]);
        }
#pragma unroll
        for (int nt = 0; nt < 8; nt++) {
            const float2 mv = *(const float2*)(smv + soff + 16384 + (8*nt + 2*(lane&3))*4);
            S[nt][0] = fmaf(S[nt][0], 0.125f, mv.x);
            S[nt][1] = fmaf(S[nt][1], 0.125f, mv.y);
            S[nt][2] = fmaf(S[nt][2], 0.125f, mv.x);
            S[nt][3] = fmaf(S[nt][3], 0.125f, mv.y);
        }
        float mx0 = -1e30f, mx1 = -1e30f;
#pragma unroll
        for (int nt = 0; nt < 8; nt++) {
            mx0 = fmaxf(mx0, fmaxf(S[nt][0], S[nt][1]));
            mx1 = fmaxf(mx1, fmaxf(S[nt][2], S[nt][3]));
        }
        mx0 = fmaxf(mx0, __shfl_xor_sync(~0u, mx0, 1));
        mx0 = fmaxf(mx0, __shfl_xor_sync(~0u, mx0, 2));
        mx1 = fmaxf(mx1, __shfl_xor_sync(~0u, mx1, 1));
        mx1 = fmaxf(mx1, __shfl_xor_sync(~0u, mx1, 2));
        const float mLn0 = fmaxf(mL0, mx0 * L2E);
        const float mLn1 = fmaxf(mL1, mx1 * L2E);
        const float corr0 = exp2f(mL0 - mLn0);
        const float corr1 = exp2f(mL1 - mLn1);
        mL0 = mLn0; mL1 = mLn1;
        lacc[0] *= corr0; lacc[1] *= corr0; lacc[2] *= corr1; lacc[3] *= corr1;
#pragma unroll
        for (int nt = 0; nt < 8; nt++) {
            o[nt][0] *= corr0; o[nt][1] *= corr0; o[nt][2] *= corr1; o[nt][3] *= corr1;
        }
        uint32_t pf[4][4];
#pragma unroll
        for (int j = 0; j < 4; j++) {
            pf[j][0] = exp2_pack(fmaf(S[2*j][1],   L2E, -mL0), fmaf(S[2*j][0],   L2E, -mL0));
            pf[j][1] = exp2_pack(fmaf(S[2*j][3],   L2E, -mL1), fmaf(S[2*j][2],   L2E, -mL1));
            pf[j][2] = exp2_pack(fmaf(S[2*j+1][1], L2E, -mL0), fmaf(S[2*j+1][0], L2E, -mL0));
            pf[j][3] = exp2_pack(fmaf(S[2*j+1][3], L2E, -mL1), fmaf(S[2*j+1][2], L2E, -mL1));
        }
#pragma unroll
        for (int j = 0; j < 4; j++) mmaf16(lacc, pf[j], ones2);
#pragma unroll
        for (int j = 0; j < 4; j++) {
            const uint32_t vbase = st + 8192 + (uint32_t)(j * 2048);
#pragma unroll
            for (int pp = 0; pp < 4; pp++) {
                uint32_t vf[4];
                ldsm4t(vf, vbase + (vboff ^ ((uint32_t)pp << 5)));
                mmaf16(o[2*pp],   pf[j], vf);
                mmaf16(o[2*pp+1], pf[j], vf + 2);
            }
        }
    }

    const float inv0 = 1.0f / lacc[0];
    const float inv1 = 1.0f / lacc[2];
    const size_t r0 = (size_t)(b*SS + q0 + wid*16 + (lane >> 2));
    const size_t r1 = r0 + 8;
#pragma unroll
    for (int nt = 0; nt < 8; nt++) {
        const size_t col = hoff + 8*nt + 2*(lane & 3);
        *(__half2*)&c16[r0*DD + col] = __halves2half2(
            __float2half_rn(o[nt][0]*inv0), __float2half_rn(o[nt][1]*inv0));
        *(__half2*)&c16[r1*DD + col] = __halves2half2(
            __float2half_rn(o[nt][2]*inv1), __float2half_rn(o[nt][3]*inv1));
    }
}

// ---- warp-per-row LayerNorm: shuffle-only, no smem/bar ----
__global__ __launch_bounds__(256)
void ln_kernel(const float* __restrict__ Y, const float* __restrict__ R,
               const float* __restrict__ g, const float* __restrict__ bta,
               float* __restrict__ out, __half* __restrict__ h16) {
    const int row = blockIdx.x * 8 + (threadIdx.x >> 5);
    const int lane = threadIdx.x & 31;
    const float4* yp = (const float4*)(Y + (size_t)row * DD);
    const float4* rp = (const float4*)(R + (size_t)row * DD);

    float4 v[8];
    float s = 0.0f;
#pragma unroll
    for (int j = 0; j < 8; j++) {
        float4 a = yp[lane + 32 * j];
        const float4 b = rp[lane + 32 * j];
        a.x += b.x; a.y += b.y; a.z += b.z; a.w += b.w;
        v[j] = a;
        s += a.x + a.y + a.z + a.w;
    }
#pragma unroll
    for (int off = 16; off; off >>= 1) s += __shfl_xor_sync(~0u, s, off);
    const float mean = s * (1.0f / 1024.0f);

    float s2 = 0.0f;
#pragma unroll
    for (int j = 0; j < 8; j++) {
        const float dx = v[j].x - mean, dy = v[j].y - mean;
        const float dz = v[j].z - mean, dw = v[j].w - mean;
        s2 += dx*dx + dy*dy + dz*dz + dw*dw;
    }
#pragma unroll
    for (int off = 16; off; off >>= 1) s2 += __shfl_xor_sync(~0u, s2, off);
    const float rstd = rsqrtf(s2 * (1.0f / 1024.0f) + 1e-12f);

    float4* op = (float4*)(out + (size_t)row * DD);
#pragma unroll
    for (int j = 0; j < 8; j++) {
        const int idx = lane + 32 * j;
        const float4 gg = ((const float4*)g)[idx];
        const float4 bb = ((const float4*)bta)[idx];
        float4 o;
        o.x = (v[j].x - mean) * rstd * gg.x + bb.x;
        o.y = (v[j].y - mean) * rstd * gg.y + bb.y;
        o.z = (v[j].z - mean) * rstd * gg.z + bb.z;
        o.w = (v[j].w - mean) * rstd * gg.w + bb.w;
        op[idx] = o;
        if (h16) {
            ((__half2*)(h16 + (size_t)row * DD))[2*idx] =
                __halves2half2(__float2half_rn(o.x), __float2half_rn(o.y));
            ((__half2*)(h16 + (size_t)row * DD))[2*idx+1] =
                __halves2half2(__float2half_rn(o.z), __float2half_rn(o.w));
        }
    }
}

extern "C" void kernel_launch(void* const* d_in, const int* in_sizes, int n_in,
                              void* d_out, int out_size) {
    const float* x    = (const float*)d_in[0];
    const float* mask = (const float*)d_in[1];
    const float* Wq = (const float*)d_in[2];  const float* bq = (const float*)d_in[3];
    const float* Wk = (const float*)d_in[4];  const float* bk = (const float*)d_in[5];
    const float* Wv = (const float*)d_in[6];  const float* bv = (const float*)d_in[7];
    const float* Wo = (const float*)d_in[8];  const float* bo = (const float*)d_in[9];
    const float* ln1g = (const float*)d_in[10]; const float* ln1b = (const float*)d_in[11];
    const float* Wi = (const float*)d_in[12]; const float* bi = (const float*)d_in[13];
    const float* Wo2 = (const float*)d_in[14]; const float* bo2 = (const float*)d_in[15];
    const float* ln2g = (const float*)d_in[16]; const float* ln2b = (const float*)d_in[17];
    float* out = (float*)d_out;

    float *tmp, *res, *b3;
    __half *x16, *ln16, *c16, *f16, *q16, *k16, *v16, *wh;
    cudaGetSymbolAddress((void**)&tmp, g_tmp);
    cudaGetSymbolAddress((void**)&res, g_res);
    cudaGetSymbolAddress((void**)&b3, g_b3);
    cudaGetSymbolAddress((void**)&x16, g_x16);
    cudaGetSymbolAddress((void**)&ln16, g_ln16);
    cudaGetSymbolAddress((void**)&c16, g_c16);
    cudaGetSymbolAddress((void**)&f16, g_f16);
    cudaGetSymbolAddress((void**)&q16, g_q16);
    cudaGetSymbolAddress((void**)&k16, g_k16);
    cudaGetSymbolAddress((void**)&v16, g_v16);
    cudaGetSymbolAddress((void**)&wh, g_wh);

    cudaFuncSetAttribute(gemm_tc, cudaFuncAttributeMaxDynamicSharedMemorySize, GSMEM);
    cudaFuncSetAttribute(attn_mma, cudaFuncAttributeMaxDynamicSharedMemorySize, AT_SMEM);

    megaprep_kernel<<<14339, 256>>>(Wq, Wk, Wv, Wo, Wi, Wo2, x, bq, bk, bv, wh, x16, b3);

    gemm_tc<<<dim3(QKVW/128, MM/128), 128, GSMEM>>>(x16, wh + W_QKV, b3,
        0, 0, q16, k16, v16, QKVW, DD, 0, 2);
    attn_mma<<<dim3(SS/128, BB*16), 256, AT_SMEM>>>(q16, k16, v16, mask, c16);
    gemm_tc<<<dim3(DD/128, MM/128), 128, GSMEM>>>(c16, wh + W_O, bo,
        tmp, 0, 0, 0, 0, DD, DD, 0, 0);
    ln_kernel<<<MM/8, 256>>>(tmp, x, ln1g, ln1b, res, ln16);
    gemm_tc<<<dim3(DFFN/128, MM/128), 128, GSMEM>>>(ln16, wh + W_I, bi,
        0, f16, 0, 0, 0, DFFN, DD, 1, 1);
    gemm_tc<<<dim3(DD/128, MM/128), 128, GSMEM>>>(f16, wh + W_O2, bo2,
        tmp, 0, 0, 0, 0, DD, DFFN, 0, 0);
    ln_kernel<<<MM/8, 256>>>(tmp, res, ln2g, ln2b, out, 0);
}

// round 16
// speedup vs baseline: 1.0735x; 1.0301x over previous
#include <cuda_runtime.h>
#include <cuda_bf16.h>
#include <cuda_fp16.h>
#include <math.h>
#include <stdint.h>

#define BB 4
#define SS 2048
#define DD 1024
#define DFFN 4096
#define MM (BB*SS)
#define QKVW 3072
#define L2E 1.44269504088896f

__device__ float g_res[(size_t)MM * DD];
__device__ __half g_x16[(size_t)MM * DD];     // x fp16, later reused as Wo/Wo2 fp16 tmp
__device__ __half g_ln16[(size_t)MM * DD];
__device__ __half g_c16[(size_t)MM * DD];
__device__ __half g_f16[(size_t)MM * DFFN];
__device__ __half g_q16[(size_t)MM * DD];
__device__ __half g_k16[(size_t)MM * DD];
__device__ __half g_v16[(size_t)MM * DD];
#define W_QKV 0u
#define W_O   (3u*1024*1024)
#define W_I   (4u*1024*1024)
#define W_O2  (8u*1024*1024)
__device__ __half g_wh[12u*1024*1024];
__device__ float g_b3[QKVW];

__device__ __forceinline__ float gelu_f(float x) {
    return 0.5f * x * (1.0f + erff(x * 0.70710678118654752f));
}
__device__ __forceinline__ uint32_t s2u(const void* p) {
    uint32_t a;
    asm("{ .reg .u64 t; cvta.to.shared.u64 t, %1; cvt.u32.u64 %0, t; }" : "=r"(a) : "l"(p));
    return a;
}
__device__ __forceinline__ uint32_t swz(uint32_t off) {
    return off ^ (((off >> 7) & 7u) << 4);
}
__device__ __forceinline__ void cpa(uint32_t dst, const void* src) {
    asm volatile("cp.async.cg.shared.global [%0], [%1], 16;" :: "r"(dst), "l"(src));
}
__device__ __forceinline__ void ldsm4(uint32_t* r, uint32_t addr) {
    asm volatile("ldmatrix.sync.aligned.m8n8.x4.shared.b16 {%0,%1,%2,%3}, [%4];"
        : "=r"(r[0]), "=r"(r[1]), "=r"(r[2]), "=r"(r[3]) : "r"(addr));
}
__device__ __forceinline__ void ldsm4t(uint32_t* r, uint32_t addr) {
    asm volatile("ldmatrix.sync.aligned.m8n8.x4.trans.shared.b16 {%0,%1,%2,%3}, [%4];"
        : "=r"(r[0]), "=r"(r[1]), "=r"(r[2]), "=r"(r[3]) : "r"(addr));
}
__device__ __forceinline__ void mmaf16(float* d, const uint32_t* a, const uint32_t* b) {
    asm volatile("mma.sync.aligned.m16n8k16.row.col.f32.f16.f16.f32 "
        "{%0,%1,%2,%3}, {%4,%5,%6,%7}, {%8,%9}, {%0,%1,%2,%3};"
        : "+f"(d[0]), "+f"(d[1]), "+f"(d[2]), "+f"(d[3])
        : "r"(a[0]), "r"(a[1]), "r"(a[2]), "r"(a[3]), "r"(b[0]), "r"(b[1]));
}
__device__ __forceinline__ uint32_t exp2_pack(float odd, float even) {
    uint32_t p, r;
    asm("cvt.rn.f16x2.f32 %0, %1, %2;" : "=r"(p) : "f"(odd), "f"(even));
    asm("ex2.approx.f16x2 %0, %1;" : "=r"(r) : "r"(p));
    return r;
}

// ---- megaprep: 6 weight transposes + x->fp16 + bias pack, ONE launch ----
__device__ __forceinline__ void wconv_tile(const float* __restrict__ W, int N, int K,
                                           __half* __restrict__ hi, int bx, int by,
                                           int tx, int ty) {
    __shared__ float t[32][33];
    const int n0 = bx * 32, k0 = by * 32;
    for (int j = ty; j < 32; j += 8) t[j][tx] = W[(size_t)(k0 + j) * N + n0 + tx];
    __syncthreads();
    for (int j = ty; j < 32; j += 8)
        hi[(size_t)(n0 + j) * K + k0 + tx] = __float2half_rn(t[tx][j]);
}

__global__ __launch_bounds__(256)
void megaprep_kernel(const float* __restrict__ Wq, const float* __restrict__ Wk,
                     const float* __restrict__ Wv, const float* __restrict__ Wo,
                     const float* __restrict__ Wi, const float* __restrict__ Wo2,
                     const float* __restrict__ x,
                     const float* __restrict__ bq, const float* __restrict__ bk,
                     const float* __restrict__ bv,
                     __half* __restrict__ wh, __half* __restrict__ x16,
                     float* __restrict__ b3) {
    const int b = blockIdx.x;
    const int tx = threadIdx.x & 31, ty = threadIdx.x >> 5;
    if (b < 4096) {
        const int which = b >> 10, idx = b & 1023;
        const int bx = idx & 31, by = idx >> 5;
        const float* W = (which == 0) ? Wq : (which == 1) ? Wk : (which == 2) ? Wv : Wo;
        __half* dst = wh + ((which < 3) ? (W_QKV + (uint32_t)which * 1048576u) : W_O);
        wconv_tile(W, DD, DD, dst, bx, by, tx, ty);
    } else if (b < 8192) {
        const int idx = b - 4096;
        wconv_tile(Wi, DFFN, DD, wh + W_I, idx & 127, idx >> 7, tx, ty);
    } else if (b < 12288) {
        const int idx = b - 8192;
        wconv_tile(Wo2, DD, DFFN, wh + W_O2, idx & 31, idx >> 5, tx, ty);
    } else if (b < 14336) {
        const int tid = threadIdx.x;
        for (int i = (b - 12288) * 256 + tid; i < MM * DD / 4; i += 2048 * 256) {
            const float4 v = ((const float4*)x)[i];
            ((__half2*)x16)[2*i+0] = __halves2half2(__float2half_rn(v.x), __float2half_rn(v.y));
            ((__half2*)x16)[2*i+1] = __halves2half2(__float2half_rn(v.z), __float2half_rn(v.w));
        }
    } else {
        const int which = b - 14336;
        const float* s = (which == 0) ? bq : (which == 1) ? bk : bv;
        for (int i = threadIdx.x; i < 1024; i += 256)
            b3[which * 1024 + i] = s[i];
    }
}

// ---- fp16 GEMM (R13 config): CTA 128x128, 256 thr, 4x2 warps, BK=64,
//      3-stage cp.async, occ 2, one sync/iter, XOR addr hoist ----
#define STG_B 32768
#define T_A  0
#define T_B  16384
#define GSMEM (3*STG_B)

__device__ __forceinline__ void load_stage(uint32_t sbase,
    const __half* __restrict__ A, const __half* __restrict__ B,
    int K, int m0, int n0, int kb) {
    for (int i = threadIdx.x; i < 1024; i += 256) {
        const int row = i >> 3, cc = (i & 7) << 3;
        const uint32_t so = swz((uint32_t)(row * 128 + cc * 2));
        cpa(sbase + T_A + so, A + (size_t)(m0 + row) * K + kb + cc);
        cpa(sbase + T_B + so, B + (size_t)(n0 + row) * K + kb + cc);
    }
}

// mode 1: C16 fp16 (+act). mode 2: q/k/v fp16 out.
__global__ __launch_bounds__(256, 2)
void gemm_tc(const __half* __restrict__ A, const __half* __restrict__ B,
             const float* __restrict__ bias,
             __half* __restrict__ C16,
             __half* __restrict__ Q16, __half* __restrict__ K16, __half* __restrict__ V16,
             int N, int K, int act, int mode) {
    extern __shared__ char smv[];
    const uint32_t sb = s2u(smv);
    const int tid = threadIdx.x, lane = tid & 31, wid = tid >> 5;
    const int wm = wid & 3, wn = wid >> 2;
    const int m0 = blockIdx.y << 7, n0 = blockIdx.x << 7;
    const int nc = K >> 6;

    float acc[2][8][4];
#pragma unroll
    for (int i = 0; i < 2; i++)
#pragma unroll
        for (int j = 0; j < 8; j++)
#pragma unroll
            for (int q = 0; q < 4; q++) acc[i][j][q] = 0.0f;

    load_stage(sb, A, B, K, m0, n0, 0);
    asm volatile("cp.async.commit_group;" ::: "memory");
    load_stage(sb + STG_B, A, B, K, m0, n0, 64);
    asm volatile("cp.async.commit_group;" ::: "memory");

    const int a_r = (lane & 15);
    const int a_c = (lane >> 4) << 3;
    const int b_r = (lane & 7) + ((lane >> 4) << 3);
    const int b_c = ((lane >> 3) & 1) << 3;

    uint32_t aoff[2], boff[4];
#pragma unroll
    for (int mt = 0; mt < 2; mt++)
        aoff[mt] = swz((uint32_t)((wm*32 + mt*16 + a_r)*128 + a_c*2));
#pragma unroll
    for (int p = 0; p < 4; p++)
        boff[p] = swz((uint32_t)((wn*64 + p*16 + b_r)*128 + b_c*2));

    for (int c = 0; c < nc; c++) {
        asm volatile("cp.async.wait_group 1;" ::: "memory");
        __syncthreads();
        if (c + 2 < nc)
            load_stage(sb + (uint32_t)((c + 2) % 3) * STG_B, A, B, K, m0, n0, (c + 2) << 6);
        asm volatile("cp.async.commit_group;" ::: "memory");

        const uint32_t stA = sb + (uint32_t)(c % 3) * STG_B + T_A;
        const uint32_t stB = sb + (uint32_t)(c % 3) * STG_B + T_B;
#pragma unroll
        for (int ks = 0; ks < 4; ks++) {
            const uint32_t kx = (uint32_t)ks << 5;
            uint32_t af[2][4], bf[8][2];
#pragma unroll
            for (int mt = 0; mt < 2; mt++)
                ldsm4(af[mt], stA + (aoff[mt] ^ kx));
#pragma unroll
            for (int p = 0; p < 4; p++) {
                uint32_t t4[4];
                ldsm4(t4, stB + (boff[p] ^ kx));
                bf[2*p][0]=t4[0]; bf[2*p][1]=t4[1]; bf[2*p+1][0]=t4[2]; bf[2*p+1][1]=t4[3];
            }
#pragma unroll
            for (int mt = 0; mt < 2; mt++)
#pragma unroll
                for (int nt = 0; nt < 8; nt++)
                    mmaf16(acc[mt][nt], af[mt], bf[nt]);
        }
    }

    const int rbase = m0 + wm * 32 + (lane >> 2);
    const int cbase = n0 + wn * 64 + ((lane & 3) << 1);
    const int region = n0 >> 10;
#pragma unroll
    for (int mt = 0; mt < 2; mt++) {
#pragma unroll
        for (int nt = 0; nt < 8; nt++) {
            const int col = cbase + nt * 8;
            const float2 bv = *(const float2*)&bias[col];
            float v0 = acc[mt][nt][0] + bv.x, v1 = acc[mt][nt][1] + bv.y;
            float v2 = acc[mt][nt][2] + bv.x, v3 = acc[mt][nt][3] + bv.y;
            if (act) { v0 = gelu_f(v0); v1 = gelu_f(v1); v2 = gelu_f(v2); v3 = gelu_f(v3); }
            const size_t r0 = (size_t)(rbase + mt * 16);
            const size_t r1 = r0 + 8;
            if (mode == 1) {
                *(__half2*)&C16[r0 * N + col] = __halves2half2(__float2half_rn(v0), __float2half_rn(v1));
                *(__half2*)&C16[r1 * N + col] = __halves2half2(__float2half_rn(v2), __float2half_rn(v3));
            } else {
                const size_t cl_ = (size_t)(col - (region << 10));
                __half* D = (region == 0) ? Q16 : (region == 1) ? K16 : V16;
                *(__half2*)&D[r0 * DD + cl_] = __halves2half2(__float2half_rn(v0), __float2half_rn(v1));
                *(__half2*)&D[r1 * DD + cl_] = __halves2half2(__float2half_rn(v2), __float2half_rn(v3));
            }
        }
    }
}

// ---- fp16 flash attention: 128 q-rows/CTA, MUFU f16x2 exp, occ 2, 1 sync/iter ----
#define AT_Q 0
#define AT_ST 16384
#define AT_SSZ 16640
#define AT_SMEM (16384 + 3*16640)

__global__ __launch_bounds__(256, 2)
void attn_mma(const __half* __restrict__ q16, const __half* __restrict__ k16,
              const __half* __restrict__ v16, const float* __restrict__ mask,
              __half* __restrict__ c16) {
    extern __shared__ char smv[];
    const uint32_t sb = s2u(smv);
    const int tid = threadIdx.x, lane = tid & 31, wid = tid >> 5;
    const int b = blockIdx.y >> 4, h = blockIdx.y & 15;
    const int q0 = blockIdx.x << 7;
    const size_t hoff = (size_t)h * 64;

    for (int i = tid; i < 1024; i += 256) {
        const int row = i >> 3, cc = i & 7;
        cpa(sb + AT_Q + swz((uint32_t)(row*128 + cc*16)),
            q16 + (size_t)(b*SS + q0 + row)*DD + hoff + cc*8);
    }
    for (int sidx = 0; sidx < 2; sidx++) {
        const int kt = sidx << 6;
        const uint32_t base = sb + AT_ST + (uint32_t)sidx * AT_SSZ;
        for (int i = tid; i < 1024; i += 256) {
            const int t = i >> 9, idx = i & 511, row = idx >> 3, cc = idx & 7;
            const __half* src = (t ? v16 : k16) + (size_t)(b*SS + kt + row)*DD + hoff + cc*8;
            cpa(base + t*8192 + swz((uint32_t)(row*128 + cc*16)), src);
        }
        if (tid < 16) cpa(base + 16384 + tid*16, mask + (size_t)b*SS + kt + tid*4);
        asm volatile("cp.async.commit_group;" ::: "memory");
    }

    uint32_t qf[4][4];
    float o[8][4], lacc[4];
    float mL0 = -1e30f, mL1 = -1e30f;
#pragma unroll
    for (int nt = 0; nt < 8; nt++) { o[nt][0]=o[nt][1]=o[nt][2]=o[nt][3]=0.f; }
    lacc[0]=lacc[1]=lacc[2]=lacc[3]=0.f;
    const uint32_t ones2[2] = {0x3C003C00u, 0x3C003C00u};

    uint32_t kboff[4];
#pragma unroll
    for (int p = 0; p < 4; p++)
        kboff[p] = swz((uint32_t)((p*16 + (lane & 7) + ((lane >> 4) << 3))*128
                                  + ((((lane >> 3) & 1) << 3)) * 2));
    const uint32_t vboff = swz((uint32_t)((lane & 15)*128 + (((lane >> 4) << 3)) * 2));

    for (int c = 0; c < SS/64; c++) {
        asm volatile("cp.async.wait_group 1;" ::: "memory");
        __syncthreads();
        if (c + 2 < SS/64) {
            const int kt = (c + 2) << 6;
            const uint32_t base = sb + AT_ST + (uint32_t)((c+2) % 3) * AT_SSZ;
            for (int i = tid; i < 1024; i += 256) {
                const int t = i >> 9, idx = i & 511, row = idx >> 3, cc = idx & 7;
                const __half* src = (t ? v16 : k16) + (size_t)(b*SS + kt + row)*DD + hoff + cc*8;
                cpa(base + t*8192 + swz((uint32_t)(row*128 + cc*16)), src);
            }
            if (tid < 16) cpa(base + 16384 + tid*16, mask + (size_t)b*SS + kt + tid*4);
        }
        asm volatile("cp.async.commit_group;" ::: "memory");

        if (c == 0) {
#pragma unroll
            for (int ks = 0; ks < 4; ks++) {
                const int row = wid*16 + (lane & 15);
                const int colb = (ks*16 + ((lane >> 4) << 3)) * 2;
                ldsm4(qf[ks], sb + AT_Q + swz((uint32_t)(row*128 + colb)));
            }
        }

        const uint32_t soff = AT_ST + (uint32_t)(c % 3) * AT_SSZ;
        const uint32_t st = sb + soff;
        float S[8][4];
#pragma unroll
        for (int nt = 0; nt < 8; nt++) { S[nt][0]=S[nt][1]=S[nt][2]=S[nt][3]=0.f; }
#pragma unroll
        for (int ks = 0; ks < 4; ks++) {
            const uint32_t kx = (uint32_t)ks << 5;
            uint32_t kb[8][2];
#pragma unroll
            for (int p = 0; p < 4; p++) {
                uint32_t t4[4];
                ldsm4(t4, st + (kboff[p] ^ kx));
                kb[2*p][0]=t4[0]; kb[2*p][1]=t4[1]; kb[2*p+1][0]=t4[2]; kb[2*p+1][1]=t4[3];
            }
#pragma unroll
            for (int nt = 0; nt < 8; nt++)
                mmaf16(S[nt], qf[ks], kb[nt]);
        }
#pragma unroll
        for (int nt = 0; nt < 8; nt++) {
            const float2 mv = *(const float2*)(smv + soff + 16384 + (8*nt + 2*(lane&3))*4);
            S[nt][0] = fmaf(S[nt][0], 0.125f, mv.x);
            S[nt][1] = fmaf(S[nt][1], 0.125f, mv.y);
            S[nt][2] = fmaf(S[nt][2], 0.125f, mv.x);
            S[nt][3] = fmaf(S[nt][3], 0.125f, mv.y);
        }
        float mx0 = -1e30f, mx1 = -1e30f;
#pragma unroll
        for (int nt = 0; nt < 8; nt++) {
            mx0 = fmaxf(mx0, fmaxf(S[nt][0], S[nt][1]));
            mx1 = fmaxf(mx1, fmaxf(S[nt][2], S[nt][3]));
        }
        mx0 = fmaxf(mx0, __shfl_xor_sync(~0u, mx0, 1));
        mx0 = fmaxf(mx0, __shfl_xor_sync(~0u, mx0, 2));
        mx1 = fmaxf(mx1, __shfl_xor_sync(~0u, mx1, 1));
        mx1 = fmaxf(mx1, __shfl_xor_sync(~0u, mx1, 2));
        const float mLn0 = fmaxf(mL0, mx0 * L2E);
        const float mLn1 = fmaxf(mL1, mx1 * L2E);
        const float corr0 = exp2f(mL0 - mLn0);
        const float corr1 = exp2f(mL1 - mLn1);
        mL0 = mLn0; mL1 = mLn1;
        lacc[0] *= corr0; lacc[1] *= corr0; lacc[2] *= corr1; lacc[3] *= corr1;
#pragma unroll
        for (int nt = 0; nt < 8; nt++) {
            o[nt][0] *= corr0; o[nt][1] *= corr0; o[nt][2] *= corr1; o[nt][3] *= corr1;
        }
        uint32_t pf[4][4];
#pragma unroll
        for (int j = 0; j < 4; j++) {
            pf[j][0] = exp2_pack(fmaf(S[2*j][1],   L2E, -mL0), fmaf(S[2*j][0],   L2E, -mL0));
            pf[j][1] = exp2_pack(fmaf(S[2*j][3],   L2E, -mL1), fmaf(S[2*j][2],   L2E, -mL1));
            pf[j][2] = exp2_pack(fmaf(S[2*j+1][1], L2E, -mL0), fmaf(S[2*j+1][0], L2E, -mL0));
            pf[j][3] = exp2_pack(fmaf(S[2*j+1][3], L2E, -mL1), fmaf(S[2*j+1][2], L2E, -mL1));
        }
#pragma unroll
        for (int j = 0; j < 4; j++) mmaf16(lacc, pf[j], ones2);
#pragma unroll
        for (int j = 0; j < 4; j++) {
            const uint32_t vbase = st + 8192 + (uint32_t)(j * 2048);
#pragma unroll
            for (int pp = 0; pp < 4; pp++) {
                uint32_t vf[4];
                ldsm4t(vf, vbase + (vboff ^ ((uint32_t)pp << 5)));
                mmaf16(o[2*pp],   pf[j], vf);
                mmaf16(o[2*pp+1], pf[j], vf + 2);
            }
        }
    }

    const float inv0 = 1.0f / lacc[0];
    const float inv1 = 1.0f / lacc[2];
    const size_t r0 = (size_t)(b*SS + q0 + wid*16 + (lane >> 2));
    const size_t r1 = r0 + 8;
#pragma unroll
    for (int nt = 0; nt < 8; nt++) {
        const size_t col = hoff + 8*nt + 2*(lane & 3);
        *(__half2*)&c16[r0*DD + col] = __halves2half2(
            __float2half_rn(o[nt][0]*inv0), __float2half_rn(o[nt][1]*inv0));
        *(__half2*)&c16[r1*DD + col] = __halves2half2(
            __float2half_rn(o[nt][2]*inv1), __float2half_rn(o[nt][3]*inv1));
    }
}

// ---- warp-per-row LayerNorm: fp16 Y + fp32 residual, shuffle-only ----
__global__ __launch_bounds__(256)
void ln_kernel(const __half* __restrict__ Y16, const float* __restrict__ R,
               const float* __restrict__ g, const float* __restrict__ bta,
               float* __restrict__ out, __half* __restrict__ h16) {
    const int row = blockIdx.x * 8 + (threadIdx.x >> 5);
    const int lane = threadIdx.x & 31;
    const __half2* yp = (const __half2*)(Y16 + (size_t)row * DD);
    const float4* rp = (const float4*)(R + (size_t)row * DD);

    float4 v[8];
    float s = 0.0f;
#pragma unroll
    for (int j = 0; j < 8; j++) {
        const int idx = lane + 32 * j;
        const float2 y0 = __half22float2(yp[2*idx]);
        const float2 y1 = __half22float2(yp[2*idx+1]);
        const float4 b = rp[idx];
        float4 a;
        a.x = y0.x + b.x; a.y = y0.y + b.y; a.z = y1.x + b.z; a.w = y1.y + b.w;
        v[j] = a;
        s += a.x + a.y + a.z + a.w;
    }
#pragma unroll
    for (int off = 16; off; off >>= 1) s += __shfl_xor_sync(~0u, s, off);
    const float mean = s * (1.0f / 1024.0f);

    float s2 = 0.0f;
#pragma unroll
    for (int j = 0; j < 8; j++) {
        const float dx = v[j].x - mean, dy = v[j].y - mean;
        const float dz = v[j].z - mean, dw = v[j].w - mean;
        s2 += dx*dx + dy*dy + dz*dz + dw*dw;
    }
#pragma unroll
    for (int off = 16; off; off >>= 1) s2 += __shfl_xor_sync(~0u, s2, off);
    const float rstd = rsqrtf(s2 * (1.0f / 1024.0f) + 1e-12f);

    float4* op = (float4*)(out + (size_t)row * DD);
#pragma unroll
    for (int j = 0; j < 8; j++) {
        const int idx = lane + 32 * j;
        const float4 gg = ((const float4*)g)[idx];
        const float4 bb = ((const float4*)bta)[idx];
        float4 o;
        o.x = (v[j].x - mean) * rstd * gg.x + bb.x;
        o.y = (v[j].y - mean) * rstd * gg.y + bb.y;
        o.z = (v[j].z - mean) * rstd * gg.z + bb.z;
        o.w = (v[j].w - mean) * rstd * gg.w + bb.w;
        op[idx] = o;
        if (h16) {
            ((__half2*)(h16 + (size_t)row * DD))[2*idx] =
                __halves2half2(__float2half_rn(o.x), __float2half_rn(o.y));
            ((__half2*)(h16 + (size_t)row * DD))[2*idx+1] =
                __halves2half2(__float2half_rn(o.z), __float2half_rn(o.w));
        }
    }
}

extern "C" void kernel_launch(void* const* d_in, const int* in_sizes, int n_in,
                              void* d_out, int out_size) {
    const float* x    = (const float*)d_in[0];
    const float* mask = (const float*)d_in[1];
    const float* Wq = (const float*)d_in[2];  const float* bq = (const float*)d_in[3];
    const float* Wk = (const float*)d_in[4];  const float* bk = (const float*)d_in[5];
    const float* Wv = (const float*)d_in[6];  const float* bv = (const float*)d_in[7];
    const float* Wo = (const float*)d_in[8];  const float* bo = (const float*)d_in[9];
    const float* ln1g = (const float*)d_in[10]; const float* ln1b = (const float*)d_in[11];
    const float* Wi = (const float*)d_in[12]; const float* bi = (const float*)d_in[13];
    const float* Wo2 = (const float*)d_in[14]; const float* bo2 = (const float*)d_in[15];
    const float* ln2g = (const float*)d_in[16]; const float* ln2b = (const float*)d_in[17];
    float* out = (float*)d_out;

    float *res, *b3;
    __half *x16, *ln16, *c16, *f16, *q16, *k16, *v16, *wh;
    cudaGetSymbolAddress((void**)&res, g_res);
    cudaGetSymbolAddress((void**)&b3, g_b3);
    cudaGetSymbolAddress((void**)&x16, g_x16);
    cudaGetSymbolAddress((void**)&ln16, g_ln16);
    cudaGetSymbolAddress((void**)&c16, g_c16);
    cudaGetSymbolAddress((void**)&f16, g_f16);
    cudaGetSymbolAddress((void**)&q16, g_q16);
    cudaGetSymbolAddress((void**)&k16, g_k16);
    cudaGetSymbolAddress((void**)&v16, g_v16);
    cudaGetSymbolAddress((void**)&wh, g_wh);

    cudaFuncSetAttribute(gemm_tc, cudaFuncAttributeMaxDynamicSharedMemorySize, GSMEM);
    cudaFuncSetAttribute(attn_mma, cudaFuncAttributeMaxDynamicSharedMemorySize, AT_SMEM);

    megaprep_kernel<<<14339, 256>>>(Wq, Wk, Wv, Wo, Wi, Wo2, x, bq, bk, bv, wh, x16, b3);

    // QKV (reads x16 before it is reused as tmp)
    gemm_tc<<<dim3(QKVW/128, MM/128), 256, GSMEM>>>(x16, wh + W_QKV, b3,
        0, q16, k16, v16, QKVW, DD, 0, 2);
    attn_mma<<<dim3(SS/128, BB*16), 256, AT_SMEM>>>(q16, k16, v16, mask, c16);
    // ctx @ Wo -> fp16 tmp (reuse x16)
    gemm_tc<<<dim3(DD/128, MM/128), 256, GSMEM>>>(c16, wh + W_O, bo,
        x16, 0, 0, 0, DD, DD, 0, 1);
    ln_kernel<<<MM/8, 256>>>(x16, x, ln1g, ln1b, res, ln16);
    gemm_tc<<<dim3(DFFN/128, MM/128), 256, GSMEM>>>(ln16, wh + W_I, bi,
        f16, 0, 0, 0, DFFN, DD, 1, 1);
    // ffn @ Wo2 -> fp16 tmp (reuse x16)
    gemm_tc<<<dim3(DD/128, MM/128), 256, GSMEM>>>(f16, wh + W_O2, bo2,
        x16, 0, 0, 0, DD, DFFN, 0, 1);
    ln_kernel<<<MM/8, 256>>>(x16, res, ln2g, ln2b, out, 0);
}